// round 10
// baseline (speedup 1.0000x reference)
#include <cuda_runtime.h>
#include <cstdint>

typedef unsigned long long u64;

#define MAXN   16384
#define NCELL  512           // 8x8x8 cells of 5 Angstrom
#define CAP    128           // bucket capacity per cell (expected ~32)
#define NB_CAP 2560          // smem neighborhood capacity (float4) = 40KB
#define NBIN   4096          // histogram bins = top 12 bits of ordered key
#define CAND   2048          // candidate buffer for final sort
#define CLN    8             // cluster size (select runs on cluster 0)
#define NBLK   256           // total CTAs (co-resident: >=3/SM x 148 = 444)
#define NTHR   512

// ---------------- scratch (device globals, zero-initialized at load) --------
__device__ float        g_mind[MAXN];
__device__ int          g_counts[MAXN];        // only far atoms' entries read
__device__ int          g_cellcnt[NCELL];      // reset in select phase each run
__device__ float4       g_bucket[NCELL * CAP];
__device__ int          g_bucketidx[NCELL * CAP];
__device__ int          g_maxcount;            // reset in select phase each run
__device__ __align__(16) int g_hist[NBIN];     // reset in select phase each run
__device__ u64          g_cand[CAND];
__device__ int          g_sA, g_sB;            // compaction counters
__device__ unsigned int g_arrive;              // grid barrier (self-resetting)
__device__ unsigned int g_gen;                 // monotonic across replays

__constant__ float c_bond[20] = {
    1.05f, 1.3f, 1.1f, 1.2f, 1.0f, 1.1f, 1.2f, 1.0f, 1.4f, 1.0f,
    1.0f,  1.3f, 1.0f, 1.5f, 1.0f, 1.05f, 1.05f, 1.6f, 1.4f, 1.1f
};

// ---------------- grid barrier (all NBLK blocks co-resident) -----------------
__device__ __forceinline__ void grid_bar(unsigned int& mygen) {
    __syncthreads();
    if (threadIdx.x == 0) {
        __threadfence();
        unsigned int a = atomicAdd(&g_arrive, 1u);
        if (a == NBLK - 1) {
            g_arrive = 0;
            __threadfence();
            *(volatile unsigned int*)&g_gen = mygen + 1u;
        } else {
            while (*(volatile unsigned int*)&g_gen == mygen) { }
        }
        __threadfence();
    }
    __syncthreads();
    mygen++;
}

// ---------------- cluster sync (global-memory producer/consumer safe) --------
__device__ __forceinline__ void cluster_sync_gl() {
    __syncthreads();
    __threadfence();
    asm volatile("barrier.cluster.arrive.aligned;" ::: "memory");
    asm volatile("barrier.cluster.wait.aligned;"   ::: "memory");
    __threadfence();
}

__device__ __forceinline__ u64 umax64(u64 a, u64 b) { return a > b ? a : b; }
__device__ __forceinline__ u64 umin64(u64 a, u64 b) { return a < b ? a : b; }

__device__ __forceinline__ void cas_shfl(u64& v, int j, bool desc, int t) {
    u64 u = __shfl_xor_sync(0xffffffffu, v, j);
    bool keepmax = (((t & j) == 0) == desc);
    v = keepmax ? umax64(v, u) : umin64(v, u);
}

__device__ __forceinline__ void cas_smem(u64& v, u64* s, int j, bool desc, int t) {
    s[t] = v;
    __syncthreads();
    u64 u = s[t ^ j];
    bool keepmax = (((t & j) == 0) == desc);
    v = keepmax ? umax64(v, u) : umin64(v, u);
    __syncthreads();
}

// full descending bitonic sort of 512 elements, thread t owns v
__device__ __forceinline__ void bitonic512_desc(u64& v, u64* s, int t) {
    #pragma unroll
    for (int k = 2; k <= 32; k <<= 1) {
        bool desc = ((t & k) == 0);
        #pragma unroll
        for (int j = k >> 1; j > 0; j >>= 1) cas_shfl(v, j, desc, t);
    }
    #pragma unroll
    for (int k = 64; k <= 512; k <<= 1) {
        bool desc = ((t & k) == 0);
        for (int j = k >> 1; j >= 32; j >>= 1) cas_smem(v, s, j, desc, t);
        #pragma unroll
        for (int j = 16; j > 0; j >>= 1) cas_shfl(v, j, desc, t);
    }
}

// descending bitonic MERGE of 512 elements (input bitonic), thread t owns v
__device__ __forceinline__ void bimerge512_desc(u64& v, u64* s, int t) {
    for (int j = 256; j >= 32; j >>= 1) cas_smem(v, s, j, true, t);
    #pragma unroll
    for (int j = 16; j > 0; j >>= 1) cas_shfl(v, j, true, t);
}

// ---------------- shared memory (phases are disjoint in time) ----------------
struct SmemAll {
    union {
        float4 lig[64];        // phase A
        float4 nb[NB_CAP];     // phase B (40KB)
        u64    k[NBIN / 2];    // phase C sort buffer / hist scan alias
    } u;
    int warpsum[16], warpsuf[16];
    int s_thr;
};

// ---------------- the single fused kernel -------------------------------------
__global__ void __cluster_dims__(CLN, 1, 1) __launch_bounds__(NTHR)
k_all(const float* __restrict__ pos, const float* __restrict__ lig,
      const float* __restrict__ x, float* __restrict__ out,
      int N, int M, int F, int K) {
    __shared__ SmemAll sm;
    unsigned int mygen = *(volatile unsigned int*)&g_gen;
    int t   = threadIdx.x;
    int blk = blockIdx.x;

    // ============ Phase A: min dist to ligand + bucket scatter ============
    // blocks 0..31 active (16384 atoms, 1 per thread)
    int ai = blk * NTHR + t;
    if (ai < N) {
        for (int q = t; q < M; q += NTHR)
            sm.u.lig[q] = make_float4(lig[3 * q + 0], lig[3 * q + 1], lig[3 * q + 2], 0.0f);
        __syncthreads();

        float px = pos[3 * ai + 0], py = pos[3 * ai + 1], pz = pos[3 * ai + 2];
        float b0 = 3.4e38f, b1 = 3.4e38f, b2 = 3.4e38f, b3 = 3.4e38f;
        #pragma unroll 4
        for (int m = 0; m < M; m += 4) {
            float4 l0 = sm.u.lig[m + 0];
            float4 l1 = sm.u.lig[m + 1];
            float4 l2 = sm.u.lig[m + 2];
            float4 l3 = sm.u.lig[m + 3];
            float dx0 = px - l0.x, dy0 = py - l0.y, dz0 = pz - l0.z;
            float dx1 = px - l1.x, dy1 = py - l1.y, dz1 = pz - l1.z;
            float dx2 = px - l2.x, dy2 = py - l2.y, dz2 = pz - l2.z;
            float dx3 = px - l3.x, dy3 = py - l3.y, dz3 = pz - l3.z;
            b0 = fminf(b0, dx0 * dx0 + dy0 * dy0 + dz0 * dz0);
            b1 = fminf(b1, dx1 * dx1 + dy1 * dy1 + dz1 * dz1);
            b2 = fminf(b2, dx2 * dx2 + dy2 * dy2 + dz2 * dz2);
            b3 = fminf(b3, dx3 * dx3 + dy3 * dy3 + dz3 * dz3);
        }
        float best = fminf(fminf(b0, b1), fminf(b2, b3));
        float d = sqrtf(fmaxf(best, 1e-12f));
        g_mind[ai] = d;

        if (d > 8.0f) {
            int cx = min((int)(px * 0.2f), 7);
            int cy = min((int)(py * 0.2f), 7);
            int cz = min((int)(pz * 0.2f), 7);
            int c  = (cz << 6) | (cy << 3) | cx;
            int r  = atomicAdd(&g_cellcnt[c], 1);
            if (r < CAP) {
                g_bucket[c * CAP + r]    = make_float4(px, py, pz, 0.0f);
                g_bucketidx[c * CAP + r] = ai;
            }
        }
    }
    grid_bar(mygen);

    // ============ Phase B: per-cell neighbor counts (2 cells per block) =======
    {
        int warp = t >> 5, lane = t & 31;
        #pragma unroll
        for (int cc = 0; cc < 2; cc++) {
            int c = blk * 2 + cc;
            int A = min(g_cellcnt[c], CAP);
            if (A > 0) {
                int cx = c & 7, cy = (c >> 3) & 7, cz = c >> 6;

                int T = 0, T0 = 0;
                for (int dz = -1; dz <= 1; dz++) {
                    int z = cz + dz; if (z < 0 || z > 7) continue;
                    for (int dy = -1; dy <= 1; dy++) {
                        int y = cy + dy; if (y < 0 || y > 7) continue;
                        for (int dx = -1; dx <= 1; dx++) {
                            int xx = cx + dx; if (xx < 0 || xx > 7) continue;
                            int nc  = (z << 6) | (y << 3) | xx;
                            int len = min(g_cellcnt[nc], CAP);
                            if (T + len > NB_CAP) len = NB_CAP - T;
                            if (nc == c) T0 = T;
                            for (int k = t; k < len; k += NTHR)
                                sm.u.nb[T + k] = g_bucket[nc * CAP + k];
                            T += len;
                        }
                    }
                }
                __syncthreads();

                int wmax = 0;
                for (int a = warp; a < A; a += (NTHR >> 5)) {
                    float4 p = sm.u.nb[T0 + a];
                    int cnt = 0;
                    for (int j = lane; j < T; j += 32) {
                        float4 q = sm.u.nb[j];
                        float dx = p.x - q.x, dy = p.y - q.y, dz = p.z - q.z;
                        float d2 = dx * dx + dy * dy + dz * dz;
                        cnt += (d2 < 25.0f && d2 > 0.0f) ? 1 : 0;
                    }
                    #pragma unroll
                    for (int o = 16; o > 0; o >>= 1)
                        cnt += __shfl_down_sync(0xffffffffu, cnt, o);
                    if (lane == 0) {
                        g_counts[g_bucketidx[c * CAP + a]] = cnt;
                        wmax = max(wmax, cnt);
                    }
                }
                if (lane == 0 && wmax > 0) atomicMax(&g_maxcount, wmax);
            }
            __syncthreads();   // protect sm.u.nb before next cell / phase
        }
    }
    grid_bar(mygen);

    // ============ Phase C: select on cluster 0 (blocks 0-7) ============
    if (blk >= CLN) return;

    u64* sh_k = sm.u.k;
    int* sh_h = (int*)sm.u.k;
    int lane = t & 31, w = t >> 5;

    // ----- C0: scores + keys (registers) + global histogram -----
    int slice = N / CLN;                       // 2048
    int base  = blk * slice;
    float mx  = (float)g_maxcount;
    mx = (mx > 0.0f) ? mx : 1.0f;
    float inv_mx = 1.0f / (mx + 1e-6f);

    u64 keys[4];
    #pragma unroll
    for (int q = 0; q < 4; q++) {
        int i = base + q * 512 + t;
        float d = g_mind[i];
        float sc;
        if (d <= 3.5f) {
            sc = 10.0f;
        } else if (d <= 8.0f) {
            sc = 5.0f * (8.0f - d) / 8.0f;
        } else {
            sc = 1.0f - (float)g_counts[i] * inv_mx;
        }
        int rt = (int)x[i * F + 1];
        rt = min(max(rt, 0), 19);
        sc *= c_bond[rt];

        out[i] = sc;

        unsigned int b = __float_as_uint(sc);
        unsigned int u = b ^ ((b >> 31) ? 0xFFFFFFFFu : 0x80000000u);
        keys[q] = ((u64)u << 32) | (u64)(0xFFFFFFFFu - (unsigned)i);
        atomicAdd(&g_hist[(int)(keys[q] >> 52)], 1);
    }
    cluster_sync_gl();

    // ----- C1: redundant threshold computation (all 8 CTAs) -----
    if (t == 0) sm.s_thr = 0;
    const int4* h4 = (const int4*)g_hist;
    int4 v0 = h4[2 * t], v1 = h4[2 * t + 1];   // bins 8t .. 8t+7
    int b8[8] = { v0.x, v0.y, v0.z, v0.w, v1.x, v1.y, v1.z, v1.w };
    int local = b8[0] + b8[1] + b8[2] + b8[3] + b8[4] + b8[5] + b8[6] + b8[7];

    int v = local;
    #pragma unroll
    for (int off = 1; off < 32; off <<= 1) {
        int u2 = __shfl_down_sync(0xffffffffu, v, off);
        if (lane + off < 32) v += u2;
    }
    if (lane == 0) sm.warpsum[w] = v;
    __syncthreads();
    if (w == 0) {
        int s = (lane < 16) ? sm.warpsum[lane] : 0;
        #pragma unroll
        for (int off = 1; off < 16; off <<= 1) {
            int u2 = __shfl_down_sync(0xffffffffu, s, off);
            if (lane + off < 16) s += u2;
        }
        if (lane < 16) sm.warpsuf[lane] = s - sm.warpsum[lane];  // exclusive suffix
    }
    __syncthreads();

    int after = (v - local) + sm.warpsuf[w];   // sum of bins >= 8*(t+1)
    int suf[8];
    suf[7] = after + b8[7];
    #pragma unroll
    for (int q = 6; q >= 0; q--) suf[q] = suf[q + 1] + b8[q];
    #pragma unroll
    for (int q = 0; q < 8; q++) sh_h[8 * t + q] = suf[q];
    __syncthreads();

    #pragma unroll
    for (int q = 0; q < 8; q++) {
        int i = 8 * t + q;
        int hb = sh_h[i];
        int hn = (i + 1 < NBIN) ? sh_h[i + 1] : 0;
        if (hb >= K && hn < K) sm.s_thr = i;   // exactly one bin matches
    }
    __syncthreads();
    int Bt    = sm.s_thr;
    int C1    = (Bt + 1 < NBIN) ? sh_h[Bt + 1] : 0;  // keys in bins > Bt (< K)
    int total = min(sh_h[Bt], CAND);
    __syncthreads();                            // sh_h done before smem reuse

    // ----- C2: two-tier compaction straight from registers -----
    #pragma unroll
    for (int q = 0; q < 4; q++) {
        int bin = (int)(keys[q] >> 52);
        if (bin >= Bt) {
            int p = (bin > Bt) ? atomicAdd(&g_sA, 1) : (C1 + atomicAdd(&g_sB, 1));
            if (p < CAND) g_cand[p] = keys[q];
        }
    }
    cluster_sync_gl();

    // ----- C3: CTAs 0-3 hybrid-sort 512-chunks; CTAs 4-7 clean state -----
    if (blk < 4) {
        int idx = blk * 512 + t;
        u64 vv = (idx < total) ? g_cand[idx] : 0ULL;  // pad: real keys have MSB set
        bitonic512_desc(vv, sh_k, t);
        g_cand[idx] = vv;
    } else {
        int o = (blk - 4) * 1024;
        g_hist[o + t]       = 0;
        g_hist[o + 512 + t] = 0;
        if (blk == 4) {
            g_cellcnt[t] = 0;                   // NCELL == NTHR == 512
            if (t == 0) { g_maxcount = 0; g_sA = 0; g_sB = 0; }
        }
    }
    cluster_sync_gl();

    // ----- C4: CTAs 0,1 merge chunk pairs (keep top 512 each) -----
    if (blk == 0) {
        u64 vv = umax64(g_cand[t], g_cand[512 + (511 - t)]);
        bimerge512_desc(vv, sh_k, t);
        g_cand[t] = vv;
    } else if (blk == 1) {
        u64 vv = umax64(g_cand[1024 + t], g_cand[1536 + (511 - t)]);
        bimerge512_desc(vv, sh_k, t);
        g_cand[1024 + t] = vv;
    }
    cluster_sync_gl();

    // ----- C5: CTA 0 final merge + unpack/write top-K -----
    if (blk == 0) {
        u64 vv = umax64(g_cand[t], g_cand[1024 + (511 - t)]);
        bimerge512_desc(vv, sh_k, t);
        if (t < K) {
            unsigned int u = (unsigned int)(vv >> 32);
            unsigned int bb = (u >> 31) ? (u ^ 0x80000000u) : (~u);
            float sc = __uint_as_float(bb);
            unsigned int idx = 0xFFFFFFFFu - (unsigned int)(vv & 0xFFFFFFFFull);
            out[N + t]     = sc;
            out[N + K + t] = (float)idx;
        }
    }
}

// ---------------- launch ------------------------------------------------------
extern "C" void kernel_launch(void* const* d_in, const int* in_sizes, int n_in,
                              void* d_out, int out_size) {
    const float* pos = (const float*)d_in[0];
    const float* lig = (const float*)d_in[1];
    const float* x   = (const float*)d_in[2];
    int N = in_sizes[0] / 3;          // 16384
    int M = in_sizes[1] / 3;          // 64
    int F = in_sizes[2] / N;          // 16
    int K = (out_size - N) / 2;       // 512
    float* out = (float*)d_out;

    k_all<<<NBLK, NTHR>>>(pos, lig, x, out, N, M, F, K);
}

// round 11
// speedup vs baseline: 1.3128x; 1.3128x over previous
#include <cuda_runtime.h>
#include <cstdint>

typedef unsigned long long u64;

#define MAXN   16384
#define NCELL  512           // 8x8x8 cells of 5 Angstrom
#define CAP    128           // bucket capacity per cell (expected ~32)
#define NB_CAP 2560          // smem neighborhood capacity (float4) = 40KB
#define NBIN   4096          // histogram bins = top 12 bits of ordered key
#define CAND   2048          // candidate buffer for final sort
#define CLN    8             // cluster size for k_select

// ---------------- scratch (device globals, zero-initialized at load) --------
__device__ float  g_score[MAXN];               // partial score (neg = far marker)
__device__ int    g_counts[MAXN];              // only far atoms' entries read
__device__ int    g_cellcnt[NCELL];            // reset in k_select each run
__device__ float4 g_bucket[NCELL * CAP];
__device__ int    g_bucketidx[NCELL * CAP];
__device__ int    g_maxcount;                  // reset in k_select each run
__device__ __align__(16) int g_hist[NBIN];     // reset in k_select each run
__device__ u64    g_cand[CAND];
__device__ int    g_sA, g_sB;                  // compaction counters, reset in k_select

__constant__ float c_bond[20] = {
    1.05f, 1.3f, 1.1f, 1.2f, 1.0f, 1.1f, 1.2f, 1.0f, 1.4f, 1.0f,
    1.0f,  1.3f, 1.0f, 1.5f, 1.0f, 1.05f, 1.05f, 1.6f, 1.4f, 1.1f
};

// ---------------- cluster sync (global-memory producer/consumer safe) --------
__device__ __forceinline__ void cluster_sync_gl() {
    __syncthreads();
    __threadfence();
    asm volatile("barrier.cluster.arrive.aligned;" ::: "memory");
    asm volatile("barrier.cluster.wait.aligned;"   ::: "memory");
    __threadfence();
}

__device__ __forceinline__ u64 umax64(u64 a, u64 b) { return a > b ? a : b; }
__device__ __forceinline__ u64 umin64(u64 a, u64 b) { return a < b ? a : b; }

__device__ __forceinline__ void cas_shfl(u64& v, int j, bool desc, int t) {
    u64 u = __shfl_xor_sync(0xffffffffu, v, j);
    bool keepmax = (((t & j) == 0) == desc);
    v = keepmax ? umax64(v, u) : umin64(v, u);
}

__device__ __forceinline__ void cas_smem(u64& v, u64* s, int j, bool desc, int t) {
    s[t] = v;
    __syncthreads();
    u64 u = s[t ^ j];
    bool keepmax = (((t & j) == 0) == desc);
    v = keepmax ? umax64(v, u) : umin64(v, u);
    __syncthreads();
}

// full descending bitonic sort of 512 elements, thread t owns v
__device__ __forceinline__ void bitonic512_desc(u64& v, u64* s, int t) {
    #pragma unroll
    for (int k = 2; k <= 32; k <<= 1) {
        bool desc = ((t & k) == 0);
        #pragma unroll
        for (int j = k >> 1; j > 0; j >>= 1) cas_shfl(v, j, desc, t);
    }
    #pragma unroll
    for (int k = 64; k <= 512; k <<= 1) {
        bool desc = ((t & k) == 0);
        for (int j = k >> 1; j >= 32; j >>= 1) cas_smem(v, s, j, desc, t);
        #pragma unroll
        for (int j = 16; j > 0; j >>= 1) cas_shfl(v, j, desc, t);
    }
}

// descending bitonic MERGE of 512 elements (input bitonic), thread t owns v
__device__ __forceinline__ void bimerge512_desc(u64& v, u64* s, int t) {
    for (int j = 256; j >= 32; j >>= 1) cas_smem(v, s, j, true, t);
    #pragma unroll
    for (int j = 16; j > 0; j >>= 1) cas_shfl(v, j, true, t);
}

// ---------------- k1: min dist + full score for near atoms + bucket scatter --
// partial score: >=0 -> final score (direct/extended); <0 -> -bond (far marker)
__global__ void __launch_bounds__(128) k_mind(const float* __restrict__ pos,
                                              const float* __restrict__ lig,
                                              const float* __restrict__ x,
                                              int N, int M, int F) {
    __shared__ float4 s_lig[64];
    for (int t = threadIdx.x; t < M; t += blockDim.x) {
        s_lig[t] = make_float4(lig[3 * t + 0], lig[3 * t + 1], lig[3 * t + 2], 0.0f);
    }
    __syncthreads();

    int i = blockIdx.x * blockDim.x + threadIdx.x;
    if (i >= N) return;

    float px = pos[3 * i + 0], py = pos[3 * i + 1], pz = pos[3 * i + 2];
    float b0 = 3.4e38f, b1 = 3.4e38f, b2 = 3.4e38f, b3 = 3.4e38f;
    #pragma unroll 4
    for (int m = 0; m < M; m += 4) {
        float4 l0 = s_lig[m + 0];
        float4 l1 = s_lig[m + 1];
        float4 l2 = s_lig[m + 2];
        float4 l3 = s_lig[m + 3];
        float dx0 = px - l0.x, dy0 = py - l0.y, dz0 = pz - l0.z;
        float dx1 = px - l1.x, dy1 = py - l1.y, dz1 = pz - l1.z;
        float dx2 = px - l2.x, dy2 = py - l2.y, dz2 = pz - l2.z;
        float dx3 = px - l3.x, dy3 = py - l3.y, dz3 = pz - l3.z;
        b0 = fminf(b0, dx0 * dx0 + dy0 * dy0 + dz0 * dz0);
        b1 = fminf(b1, dx1 * dx1 + dy1 * dy1 + dz1 * dz1);
        b2 = fminf(b2, dx2 * dx2 + dy2 * dy2 + dz2 * dz2);
        b3 = fminf(b3, dx3 * dx3 + dy3 * dy3 + dz3 * dz3);
    }
    float best = fminf(fminf(b0, b1), fminf(b2, b3));
    float d = sqrtf(fmaxf(best, 1e-12f));

    int rt = (int)x[i * F + 1];
    rt = min(max(rt, 0), 19);
    float bond = c_bond[rt];

    float ps;
    if (d <= 3.5f) {
        ps = 10.0f;
        ps *= bond;
    } else if (d <= 8.0f) {
        ps = 5.0f * (8.0f - d) / 8.0f;
        ps *= bond;
    } else {
        ps = -bond;                        // far marker
        int cx = min((int)(px * 0.2f), 7);
        int cy = min((int)(py * 0.2f), 7);
        int cz = min((int)(pz * 0.2f), 7);
        int c  = (cz << 6) | (cy << 3) | cx;
        int r  = atomicAdd(&g_cellcnt[c], 1);
        if (r < CAP) {
            g_bucket[c * CAP + r]    = make_float4(px, py, pz, 0.0f);
            g_bucketidx[c * CAP + r] = i;
        }
    }
    g_score[i] = ps;
}

// ---------------- k2: per-cell neighbor counts (27-cell smem gather) ---------
__global__ void __launch_bounds__(256) k_counts() {
    __shared__ float4 s_nb[NB_CAP];

    int c = blockIdx.x;
    int A = min(g_cellcnt[c], CAP);
    if (A == 0) return;

    int cx = c & 7, cy = (c >> 3) & 7, cz = c >> 6;

    int T = 0, T0 = 0;
    for (int dz = -1; dz <= 1; dz++) {
        int z = cz + dz; if (z < 0 || z > 7) continue;
        for (int dy = -1; dy <= 1; dy++) {
            int y = cy + dy; if (y < 0 || y > 7) continue;
            for (int dx = -1; dx <= 1; dx++) {
                int x = cx + dx; if (x < 0 || x > 7) continue;
                int nc  = (z << 6) | (y << 3) | x;
                int len = min(g_cellcnt[nc], CAP);
                if (T + len > NB_CAP) len = NB_CAP - T;  // safety clamp
                if (nc == c) T0 = T;
                for (int k = threadIdx.x; k < len; k += blockDim.x)
                    s_nb[T + k] = g_bucket[nc * CAP + k];
                T += len;
            }
        }
    }
    __syncthreads();

    int warp = threadIdx.x >> 5, lane = threadIdx.x & 31;
    int nwarps = blockDim.x >> 5;
    int wmax = 0;
    for (int a = warp; a < A; a += nwarps) {
        float4 p = s_nb[T0 + a];
        int cnt = 0;
        for (int j = lane; j < T; j += 32) {
            float4 q = s_nb[j];
            float dx = p.x - q.x, dy = p.y - q.y, dz = p.z - q.z;
            float d2 = dx * dx + dy * dy + dz * dz;
            cnt += (d2 < 25.0f && d2 > 0.0f) ? 1 : 0;
        }
        #pragma unroll
        for (int o = 16; o > 0; o >>= 1)
            cnt += __shfl_down_sync(0xffffffffu, cnt, o);
        if (lane == 0) {
            g_counts[g_bucketidx[c * CAP + a]] = cnt;
            wmax = max(wmax, cnt);
        }
    }
    if (lane == 0 && wmax > 0) atomicMax(&g_maxcount, wmax);
}

// ---------------- k3: fused score-finish/hist/threshold/compact/sort/write ---
__global__ void __cluster_dims__(CLN, 1, 1) __launch_bounds__(512)
k_select(float* __restrict__ out, int N, int K) {
    __shared__ u64 sh_u64[NBIN / 2];           // 16KB; int[4096] alias for hist scan
    int* sh_h = (int*)sh_u64;
    __shared__ int warpsum[16], warpsuf[16];
    __shared__ int s_thr;

    int t = threadIdx.x, lane = t & 31, w = t >> 5;
    int blk = blockIdx.x;                      // == cluster rank (grid = 1 cluster)

    // ===== Phase 0: finish far scores + keys (registers) + histogram =====
    int slice = N / CLN;                       // 2048
    int base  = blk * slice;
    float mx  = (float)g_maxcount;
    mx = (mx > 0.0f) ? mx : 1.0f;
    float inv_mx = 1.0f / (mx + 1e-6f);

    u64 keys[4];
    #pragma unroll
    for (int q = 0; q < 4; q++) {
        int i = base + q * 512 + t;
        float ps = g_score[i];
        float sc;
        if (ps >= 0.0f) {
            sc = ps;                           // direct/extended: already final
        } else {
            sc = 1.0f - (float)g_counts[i] * inv_mx;
            sc *= -ps;                         // -ps == bond, exact
        }
        out[i] = sc;

        unsigned int b = __float_as_uint(sc);
        unsigned int u = b ^ ((b >> 31) ? 0xFFFFFFFFu : 0x80000000u);
        keys[q] = ((u64)u << 32) | (u64)(0xFFFFFFFFu - (unsigned)i);
        atomicAdd(&g_hist[(int)(keys[q] >> 52)], 1);
    }
    cluster_sync_gl();

    // ===== Phase 1: redundant threshold computation (all CTAs) =====
    if (t == 0) s_thr = 0;
    const int4* h4 = (const int4*)g_hist;
    int4 v0 = h4[2 * t], v1 = h4[2 * t + 1];   // bins 8t .. 8t+7
    int b8[8] = { v0.x, v0.y, v0.z, v0.w, v1.x, v1.y, v1.z, v1.w };
    int local = b8[0] + b8[1] + b8[2] + b8[3] + b8[4] + b8[5] + b8[6] + b8[7];

    int v = local;
    #pragma unroll
    for (int off = 1; off < 32; off <<= 1) {
        int u2 = __shfl_down_sync(0xffffffffu, v, off);
        if (lane + off < 32) v += u2;
    }
    if (lane == 0) warpsum[w] = v;
    __syncthreads();
    if (w == 0) {
        int s = (lane < 16) ? warpsum[lane] : 0;
        #pragma unroll
        for (int off = 1; off < 16; off <<= 1) {
            int u2 = __shfl_down_sync(0xffffffffu, s, off);
            if (lane + off < 16) s += u2;
        }
        if (lane < 16) warpsuf[lane] = s - warpsum[lane];  // exclusive suffix
    }
    __syncthreads();

    int after = (v - local) + warpsuf[w];      // sum of bins >= 8*(t+1)
    int suf[8];
    suf[7] = after + b8[7];
    #pragma unroll
    for (int q = 6; q >= 0; q--) suf[q] = suf[q + 1] + b8[q];
    #pragma unroll
    for (int q = 0; q < 8; q++) sh_h[8 * t + q] = suf[q];
    __syncthreads();

    #pragma unroll
    for (int q = 0; q < 8; q++) {
        int i = 8 * t + q;
        int hb = sh_h[i];
        int hn = (i + 1 < NBIN) ? sh_h[i + 1] : 0;
        if (hb >= K && hn < K) s_thr = i;      // exactly one bin matches
    }
    __syncthreads();
    int Bt    = s_thr;
    int C1    = (Bt + 1 < NBIN) ? sh_h[Bt + 1] : 0;  // keys in bins > Bt (< K)
    int total = min(sh_h[Bt], CAND);
    __syncthreads();                            // sh_h done before smem reuse
    bool shortpath = (total <= 1024);           // uniform across all CTAs

    // ===== Phase 2: two-tier compaction straight from registers =====
    #pragma unroll
    for (int q = 0; q < 4; q++) {
        int bin = (int)(keys[q] >> 52);
        if (bin >= Bt) {
            int p = (bin > Bt) ? atomicAdd(&g_sA, 1) : (C1 + atomicAdd(&g_sB, 1));
            if (p < CAND) g_cand[p] = keys[q];
        }
    }
    cluster_sync_gl();

    // ===== Phase 3: sort chunks (2 or 4 CTAs); CTAs 4-7 clean state =====
    int nsort = shortpath ? 2 : 4;
    if (blk < nsort) {
        int idx = blk * 512 + t;
        u64 vv = (idx < total) ? g_cand[idx] : 0ULL;  // pad: real keys have MSB set
        bitonic512_desc(vv, sh_u64, t);
        g_cand[idx] = vv;
    } else if (blk >= 4) {
        int o = (blk - 4) * 1024;
        g_hist[o + t]       = 0;
        g_hist[o + 512 + t] = 0;
        if (blk == 4) {
            g_cellcnt[t] = 0;                   // NCELL == 512 == blockDim
            if (t == 0) { g_maxcount = 0; g_sA = 0; g_sB = 0; }
        }
    }
    cluster_sync_gl();

    if (shortpath) {
        // ===== Short path: CTA 0 merges the 2 runs + writes top-K =====
        if (blk == 0) {
            u64 vv = umax64(g_cand[t], g_cand[512 + (511 - t)]);
            bimerge512_desc(vv, sh_u64, t);
            if (t < K) {
                unsigned int u = (unsigned int)(vv >> 32);
                unsigned int bb = (u >> 31) ? (u ^ 0x80000000u) : (~u);
                float sc = __uint_as_float(bb);
                unsigned int idx = 0xFFFFFFFFu - (unsigned int)(vv & 0xFFFFFFFFull);
                out[N + t]     = sc;
                out[N + K + t] = (float)idx;
            }
        }
        return;
    }

    // ===== Long path: pair merges then final =====
    if (blk == 0) {
        u64 vv = umax64(g_cand[t], g_cand[512 + (511 - t)]);
        bimerge512_desc(vv, sh_u64, t);
        g_cand[t] = vv;
    } else if (blk == 1) {
        u64 vv = umax64(g_cand[1024 + t], g_cand[1536 + (511 - t)]);
        bimerge512_desc(vv, sh_u64, t);
        g_cand[1024 + t] = vv;
    }
    cluster_sync_gl();

    if (blk == 0) {
        u64 vv = umax64(g_cand[t], g_cand[1024 + (511 - t)]);
        bimerge512_desc(vv, sh_u64, t);
        if (t < K) {
            unsigned int u = (unsigned int)(vv >> 32);
            unsigned int bb = (u >> 31) ? (u ^ 0x80000000u) : (~u);
            float sc = __uint_as_float(bb);
            unsigned int idx = 0xFFFFFFFFu - (unsigned int)(vv & 0xFFFFFFFFull);
            out[N + t]     = sc;
            out[N + K + t] = (float)idx;
        }
    }
}

// ---------------- launch ------------------------------------------------------
extern "C" void kernel_launch(void* const* d_in, const int* in_sizes, int n_in,
                              void* d_out, int out_size) {
    const float* pos = (const float*)d_in[0];
    const float* lig = (const float*)d_in[1];
    const float* x   = (const float*)d_in[2];
    int N = in_sizes[0] / 3;          // 16384
    int M = in_sizes[1] / 3;          // 64
    int F = in_sizes[2] / N;          // 16
    int K = (out_size - N) / 2;       // 512
    float* out = (float*)d_out;

    k_mind<<<(N + 127) / 128, 128>>>(pos, lig, x, N, M, F);
    k_counts<<<NCELL, 256>>>();
    k_select<<<CLN, 512>>>(out, N, K);
}